// round 13
// baseline (speedup 1.0000x reference)
#include <cuda_runtime.h>
#include <cstdint>
#include <math.h>

#define BB 4
#define GG 4096
#define HD 1024
#define EE 32
#define CAP 160
#define NTOK (BB*GG)          // 16384

// Phase-A (blind fill) size: 5120 blocks * 8192 floats = 41,943,040 floats
#define A_BLOCKS 5120
#define A_FLOATS ((size_t)A_BLOCKS * 8192)

// -------- scratch (static __device__, no allocation) --------
__device__ unsigned int g_mask[NTOK];        // expert mask per token (capacity-pruned after scan)
__device__ int          g_possum[NTOK];      // sum over experts of kept positions
__device__ float        g_weights[NTOK*EE];  // expert_weights (pre-capacity)
__device__ float        g_probs[NTOK*EE];    // raw_gates (softmax probs)
__device__ int          g_density[BB*EE];    // kept count per (b,e) = min(count,CAP)
__device__ float        g_term[BB*EE];       // proxySum * kept

// ============================================================
// Kernel Za: blind zero-fill of region A (runs during compute).
// 256 thr x 8 float4 = 32KB contiguous per block. __stwt probe:
// write-through, bypassing L2 dirty-writeback path.
// ============================================================
#define FILL_TPB 256
#define FILL_CHUNK 8

__global__ __launch_bounds__(FILL_TPB) void fill_kernel(float4* __restrict__ out) {
    size_t base = (size_t)blockIdx.x * (FILL_TPB * FILL_CHUNK) + threadIdx.x;
    float4 z = make_float4(0.f, 0.f, 0.f, 0.f);
#pragma unroll
    for (int i = 0; i < FILL_CHUNK; i++)
        __stwt(&out[base + (size_t)i * FILL_TPB], z);
}

// ============================================================
// Kernel Zb: fused fill of region B [A_FLOATS, 2D) — writes
// zeros AND the correct nonzero dispatch/combine values inline.
// Per float4: row=(q4 mod D4)/40, check mask/possum, place value.
// ============================================================
__global__ __launch_bounds__(FILL_TPB) void fused_fill_kernel(float4* __restrict__ out4,
                                                              unsigned int D4) {
    unsigned int idx0 = (unsigned int)(A_FLOATS / 4)
                      + blockIdx.x * (FILL_TPB * FILL_CHUNK) + threadIdx.x;
#pragma unroll
    for (int i = 0; i < FILL_CHUNK; i++) {
        unsigned int q4 = idx0 + i * FILL_TPB;
        bool comb = q4 >= D4;
        unsigned int r4 = comb ? q4 - D4 : q4;
        unsigned int row = r4 / 40u;          // (tok*32 + e), row = 160 floats = 40 float4
        unsigned int f4  = r4 - row * 40u;    // float4 index within row
        int tok = row >> 5;
        unsigned wm = g_mask[tok];
        int ps = g_possum[tok];
        float4 v = make_float4(0.f, 0.f, 0.f, 0.f);
        if (((wm >> (row & 31u)) & 1u) && ps < CAP && (unsigned)(ps >> 2) == f4) {
            float val = comb ? g_weights[row] : 1.0f;
            reinterpret_cast<float*>(&v)[ps & 3] = val;
        }
        __stwt(&out4[q4], v);
    }
}

// ============================================================
// Kernel 1: gating — logits GEMM + softmax + stable bitonic
// sort + dynamic-k + weights/mask. Streaming loads (__ldcs) so
// the 67MB x-read doesn't evict the fill's L2 write lines.
// ============================================================
#define TPB 256
#define WARPS 8
#define TPW 4
#define TOKS_BLK (WARPS*TPW)      // 32 tokens/block

extern __shared__ float xs[];     // [32][1024] = 131072 B

__global__ __launch_bounds__(TPB) void gating_kernel(const float* __restrict__ x,
                                                     const float* __restrict__ w) {
    int tid = threadIdx.x;
    int token0 = blockIdx.x * TOKS_BLK;

    const float4* xg = (const float4*)(x + (size_t)token0 * HD);
    float4* xs4 = (float4*)xs;
#pragma unroll
    for (int i = 0; i < 32; i++) xs4[tid + i*TPB] = __ldcs(&xg[tid + i*TPB]);
    __syncthreads();

    int warp = tid >> 5, lane = tid & 31;
    float a0[TPW], a1[TPW], a2[TPW], a3[TPW];
#pragma unroll
    for (int t = 0; t < TPW; t++) { a0[t]=0.f; a1[t]=0.f; a2[t]=0.f; a3[t]=0.f; }

    const float* wp = w + lane;               // column 'lane' of w [HD][EE]
    for (int c = 0; c < HD; c += 32) {
        float wreg[32];
#pragma unroll
        for (int j = 0; j < 32; j++) wreg[j] = wp[(c + j) * EE];
#pragma unroll
        for (int t = 0; t < TPW; t++) {
            const float* xr = xs + (warp*TPW + t)*HD + c;
#pragma unroll
            for (int j = 0; j < 32; j += 4) {
                float4 xv = *(const float4*)(xr + j);
                a0[t] += xv.x * wreg[j+0];
                a1[t] += xv.y * wreg[j+1];
                a2[t] += xv.z * wreg[j+2];
                a3[t] += xv.w * wreg[j+3];
            }
        }
    }

    float* wsm = xs + warp * (TPW * HD);      // reuse this warp's x region
    int*   ssm = (int*)(wsm + 32);

    for (int t = 0; t < TPW; t++) {
        int token = token0 + warp*TPW + t;
        float logit = (a0[t] + a1[t]) + (a2[t] + a3[t]);

        // softmax across warp (lane = expert)
        float m = logit;
#pragma unroll
        for (int off = 16; off; off >>= 1) m = fmaxf(m, __shfl_xor_sync(~0u, m, off));
        float p = expf(logit - m);
        float s = p;
#pragma unroll
        for (int off = 16; off; off >>= 1) s += __shfl_xor_sync(~0u, s, off);
        p = p / s;
        __stcs(&g_probs[(size_t)token * EE + lane], p);

        // stable descending bitonic sort: key (p desc, lane asc)
        float v = p; int idx = lane;
#pragma unroll
        for (int k = 2; k <= 32; k <<= 1) {
#pragma unroll
            for (int j = k >> 1; j > 0; j >>= 1) {
                float ov = __shfl_xor_sync(~0u, v,   j);
                int   oi = __shfl_xor_sync(~0u, idx, j);
                bool down   = ((lane & k) == 0);
                bool lower  = ((lane & j) == 0);
                bool ofirst = (ov > v) || (ov == v && oi < idx);
                bool keep_other = down ? (lower == ofirst) : (lower != ofirst);
                if (keep_other) { v = ov; idx = oi; }
            }
        }

        // inclusive cumsum of sorted probs
        float cum = v;
#pragma unroll
        for (int off = 1; off < 32; off <<= 1) {
            float nb = __shfl_up_sync(~0u, cum, off);
            if (lane >= off) cum += nb;
        }
        unsigned bal = __ballot_sync(~0u, cum >= 0.8f);
        int kk = bal ? __ffs(bal) : 32;
        float sel = __shfl_sync(~0u, cum, kk - 1);
        bool selected = (lane < kk);
        float wv = selected ? (v / sel) : 0.0f;

        // scatter sorted->original expert order via smem
        __syncwarp();
        wsm[idx] = wv;
        ssm[idx] = selected ? 1 : 0;
        __syncwarp();
        float myw = wsm[lane];
        int mysel = ssm[lane];
        unsigned word = __ballot_sync(~0u, mysel != 0);
        __stcs(&g_weights[(size_t)token * EE + lane], myw);
        if (lane == 0) g_mask[token] = word;
        if (lane == 1) g_possum[token] = 0;   // init for scan's atomicAdd
        __syncwarp();
    }
}

// ============================================================
// Kernel 2: per-(b,e) exclusive scan over 4096 tokens,
// capacity truncation, pos_sum accumulation, density count
// ============================================================
__global__ __launch_bounds__(256) void scan_kernel() {
    int e = blockIdx.x & 31;
    int b = blockIdx.x >> 5;
    int tid = threadIdx.x;                // 256 threads, 16 tokens each
    int base = b * GG + tid * 16;

    unsigned bits = 0;
#pragma unroll
    for (int i = 0; i < 16; i++)
        bits |= ((g_mask[base + i] >> e) & 1u) << i;
    int cnt = __popc(bits);

    int lane = tid & 31, wrp = tid >> 5;
    int inc = cnt;
#pragma unroll
    for (int off = 1; off < 32; off <<= 1) {
        int nb = __shfl_up_sync(~0u, inc, off);
        if (lane >= off) inc += nb;
    }
    __shared__ int wsum[8];
    if (lane == 31) wsum[wrp] = inc;
    __syncthreads();
    int wofs = 0, total = 0;
#pragma unroll
    for (int i = 0; i < 8; i++) {
        int v = wsum[i];
        if (i < wrp) wofs += v;
        total += v;
    }
    int run = wofs + inc - cnt;           // exclusive prefix for this thread

    for (int i = 0; i < 16; i++) {
        if ((bits >> i) & 1u) {
            int tok = base + i;
            if (run < CAP) {
                if (run > 0) atomicAdd(&g_possum[tok], run);
            } else {
                atomicAnd(&g_mask[tok], ~(1u << e));   // drop over-capacity
            }
            run++;
        }
    }
    if (tid == 0) g_density[b * EE + e] = (total < CAP) ? total : CAP;
}

// ============================================================
// Kernel 3: scatter for region A only (dispatch offsets < A_FLOATS).
// Runs on stream 0 concurrent with the fused fill (disjoint regions).
// ============================================================
__global__ __launch_bounds__(256) void scatter_A_kernel(float* __restrict__ out) {
    int idx = blockIdx.x * blockDim.x + threadIdx.x;   // token*32 + expert
    int tok = idx >> 5;
    int e   = idx & 31;
    if (tok >= NTOK) return;
    unsigned wm = g_mask[tok];
    if (!((wm >> e) & 1u)) return;
    int ps = g_possum[tok];
    if (ps >= CAP) return;
    size_t o = ((size_t)tok * EE + e) * CAP + ps;
    if (o >= A_FLOATS) return;                // region B handled by fused fill
    out[o] = 1.0f;
}

// ============================================================
// Kernel 4: per-(b,e) proxy sum * density  -> term
// ============================================================
__global__ __launch_bounds__(256) void proxy_kernel() {
    int e = blockIdx.x & 31;
    int b = blockIdx.x >> 5;
    int tid = threadIdx.x;
    float s = 0.0f;
    for (int g = tid; g < GG; g += 256)
        s += __ldcs(&g_probs[((size_t)(b * GG + g)) * EE + e]);
    int lane = tid & 31, wrp = tid >> 5;
#pragma unroll
    for (int off = 16; off; off >>= 1) s += __shfl_xor_sync(~0u, s, off);
    __shared__ float red[8];
    if (lane == 0) red[wrp] = s;
    __syncthreads();
    if (tid == 0) {
        float tot = 0.0f;
#pragma unroll
        for (int i = 0; i < 8; i++) tot += red[i];
        g_term[b * EE + e] = tot * (float)g_density[b * EE + e];
    }
}

// ============================================================
// Kernel 5: final loss = sum(term) * 2^-21  (writes out[2D] only,
// untouched by either fill phase -> runs pre-join)
// ============================================================
__global__ __launch_bounds__(128) void loss_kernel(float* __restrict__ out, size_t D) {
    int tid = threadIdx.x;
    float v = (tid < BB * EE) ? g_term[tid] : 0.0f;
    int lane = tid & 31, wrp = tid >> 5;
#pragma unroll
    for (int off = 16; off; off >>= 1) v += __shfl_xor_sync(~0u, v, off);
    __shared__ float red[4];
    if (lane == 0) red[wrp] = v;
    __syncthreads();
    if (tid == 0) {
        float tot = red[0] + red[1] + red[2] + red[3];
        out[2 * D] = tot * 4.76837158203125e-07f;
    }
}

// ============================================================
extern "C" void kernel_launch(void* const* d_in, const int* in_sizes, int n_in,
                              void* d_out, int out_size) {
    (void)in_sizes; (void)n_in;
    const float* x = (const float*)d_in[0];
    const float* w = (const float*)d_in[1];
    float* out = (float*)d_out;
    size_t D = (size_t)((out_size - 1) / 2);   // dispatch / combine each D elems, loss last

    // region B: [A_FLOATS, 2D) floats -> (2D - A_FLOATS)/8192 blocks (exactly divisible)
    int fusedBlocks = (int)((2 * D - A_FLOATS) / (FILL_TPB * FILL_CHUNK * 4));

    int prLo = 0, prHi = 0;
    cudaDeviceGetStreamPriorityRange(&prLo, &prHi);
    cudaStream_t sZ;
    cudaEvent_t eFork, eA, eC, eDone;
    cudaStreamCreateWithPriority(&sZ, cudaStreamNonBlocking, prHi);
    cudaEventCreateWithFlags(&eFork, cudaEventDisableTiming);
    cudaEventCreateWithFlags(&eA, cudaEventDisableTiming);
    cudaEventCreateWithFlags(&eC, cudaEventDisableTiming);
    cudaEventCreateWithFlags(&eDone, cudaEventDisableTiming);

    // Phase A: blind fill of region A on sZ, concurrent with compute.
    cudaEventRecord(eFork, 0);
    cudaStreamWaitEvent(sZ, eFork, 0);
    fill_kernel<<<A_BLOCKS, FILL_TPB, 0, sZ>>>((float4*)out);
    cudaEventRecord(eA, sZ);

    // Compute chain on main stream (hidden under phase A).
    cudaFuncSetAttribute(gating_kernel,
                         cudaFuncAttributeMaxDynamicSharedMemorySize, TOKS_BLK * HD * 4);
    gating_kernel<<<NTOK / TOKS_BLK, TPB, TOKS_BLK * HD * 4>>>(x, w);
    scan_kernel<<<BB * EE, 256>>>();
    cudaEventRecord(eC, 0);
    proxy_kernel<<<BB * EE, 256>>>();
    loss_kernel<<<1, 128>>>(out, D);          // out[2D] only — independent of fills

    // Phase B: fused fill of region B (zeros + values) after compute.
    cudaStreamWaitEvent(sZ, eC, 0);
    fused_fill_kernel<<<fusedBlocks, FILL_TPB, 0, sZ>>>((float4*)out, (unsigned int)(D / 4));
    cudaEventRecord(eDone, sZ);

    // Region-A scatter on stream 0, concurrent with phase B (disjoint regions).
    cudaStreamWaitEvent(0, eA, 0);
    scatter_A_kernel<<<(NTOK * EE + 255) / 256, 256>>>(out);

    // Join the fork back into the capture stream.
    cudaStreamWaitEvent(0, eDone, 0);

    cudaEventDestroy(eFork);
    cudaEventDestroy(eA);
    cudaEventDestroy(eC);
    cudaEventDestroy(eDone);
    cudaStreamDestroy(sZ);
}

// round 14
// speedup vs baseline: 1.1317x; 1.1317x over previous
#include <cuda_runtime.h>
#include <cstdint>
#include <math.h>

#define BB 4
#define GG 4096
#define HD 1024
#define EE 32
#define CAP 160
#define NTOK (BB*GG)          // 16384

// Phase-A (blind fill) size: 5120 blocks * 8192 floats = 41,943,040 floats
#define A_BLOCKS 5120
#define A_FLOATS ((size_t)A_BLOCKS * 8192)

// -------- scratch (static __device__, no allocation) --------
__device__ unsigned int g_mask[NTOK];        // expert mask per token (capacity-pruned after scan)
__device__ int          g_possum[NTOK];      // sum over experts of kept positions
__device__ float        g_weights[NTOK*EE];  // expert_weights (pre-capacity)
__device__ float        g_probs[NTOK*EE];    // raw_gates (softmax probs)
__device__ int          g_density[BB*EE];    // kept count per (b,e) = min(count,CAP)
__device__ float        g_term[BB*EE];       // proxySum * kept

// ============================================================
// Kernel Za: blind zero-fill of region A (runs during compute).
// 256 thr x 8 float4 = 32KB contiguous per block. __stcs is the
// measured-best store policy (~2.25 TB/s, the DRAM write sink).
// ============================================================
#define FILL_TPB 256
#define FILL_CHUNK 8

__global__ __launch_bounds__(FILL_TPB) void fill_kernel(float4* __restrict__ out) {
    size_t base = (size_t)blockIdx.x * (FILL_TPB * FILL_CHUNK) + threadIdx.x;
    float4 z = make_float4(0.f, 0.f, 0.f, 0.f);
#pragma unroll
    for (int i = 0; i < FILL_CHUNK; i++)
        __stcs(&out[base + (size_t)i * FILL_TPB], z);
}

// ============================================================
// Kernel Zb: fused fill of region B [A_FLOATS, 2D) — writes
// zeros AND the correct nonzero dispatch/combine values inline.
// Per float4: row=(q4 mod D4)/40, check mask/possum, place value.
// ============================================================
__global__ __launch_bounds__(FILL_TPB) void fused_fill_kernel(float4* __restrict__ out4,
                                                              unsigned int D4) {
    unsigned int idx0 = (unsigned int)(A_FLOATS / 4)
                      + blockIdx.x * (FILL_TPB * FILL_CHUNK) + threadIdx.x;
#pragma unroll
    for (int i = 0; i < FILL_CHUNK; i++) {
        unsigned int q4 = idx0 + i * FILL_TPB;
        bool comb = q4 >= D4;
        unsigned int r4 = comb ? q4 - D4 : q4;
        unsigned int row = r4 / 40u;          // (tok*32 + e), row = 160 floats = 40 float4
        unsigned int f4  = r4 - row * 40u;    // float4 index within row
        int tok = row >> 5;
        unsigned wm = g_mask[tok];
        int ps = g_possum[tok];
        float4 v = make_float4(0.f, 0.f, 0.f, 0.f);
        if (((wm >> (row & 31u)) & 1u) && ps < CAP && (unsigned)(ps >> 2) == f4) {
            float val = comb ? g_weights[row] : 1.0f;
            reinterpret_cast<float*>(&v)[ps & 3] = val;
        }
        __stcs(&out4[q4], v);
    }
}

// ============================================================
// Kernel 1: gating — logits GEMM + softmax + stable bitonic
// sort + dynamic-k + weights/mask. Streaming loads (__ldcs) so
// the 67MB x-read doesn't evict the fill's L2 write lines.
// ============================================================
#define TPB 256
#define WARPS 8
#define TPW 4
#define TOKS_BLK (WARPS*TPW)      // 32 tokens/block

extern __shared__ float xs[];     // [32][1024] = 131072 B

__global__ __launch_bounds__(TPB) void gating_kernel(const float* __restrict__ x,
                                                     const float* __restrict__ w) {
    int tid = threadIdx.x;
    int token0 = blockIdx.x * TOKS_BLK;

    const float4* xg = (const float4*)(x + (size_t)token0 * HD);
    float4* xs4 = (float4*)xs;
#pragma unroll
    for (int i = 0; i < 32; i++) xs4[tid + i*TPB] = __ldcs(&xg[tid + i*TPB]);
    __syncthreads();

    int warp = tid >> 5, lane = tid & 31;
    float a0[TPW], a1[TPW], a2[TPW], a3[TPW];
#pragma unroll
    for (int t = 0; t < TPW; t++) { a0[t]=0.f; a1[t]=0.f; a2[t]=0.f; a3[t]=0.f; }

    const float* wp = w + lane;               // column 'lane' of w [HD][EE]
    for (int c = 0; c < HD; c += 32) {
        float wreg[32];
#pragma unroll
        for (int j = 0; j < 32; j++) wreg[j] = wp[(c + j) * EE];
#pragma unroll
        for (int t = 0; t < TPW; t++) {
            const float* xr = xs + (warp*TPW + t)*HD + c;
#pragma unroll
            for (int j = 0; j < 32; j += 4) {
                float4 xv = *(const float4*)(xr + j);
                a0[t] += xv.x * wreg[j+0];
                a1[t] += xv.y * wreg[j+1];
                a2[t] += xv.z * wreg[j+2];
                a3[t] += xv.w * wreg[j+3];
            }
        }
    }

    float* wsm = xs + warp * (TPW * HD);      // reuse this warp's x region
    int*   ssm = (int*)(wsm + 32);

    for (int t = 0; t < TPW; t++) {
        int token = token0 + warp*TPW + t;
        float logit = (a0[t] + a1[t]) + (a2[t] + a3[t]);

        // softmax across warp (lane = expert)
        float m = logit;
#pragma unroll
        for (int off = 16; off; off >>= 1) m = fmaxf(m, __shfl_xor_sync(~0u, m, off));
        float p = expf(logit - m);
        float s = p;
#pragma unroll
        for (int off = 16; off; off >>= 1) s += __shfl_xor_sync(~0u, s, off);
        p = p / s;
        __stcs(&g_probs[(size_t)token * EE + lane], p);

        // stable descending bitonic sort: key (p desc, lane asc)
        float v = p; int idx = lane;
#pragma unroll
        for (int k = 2; k <= 32; k <<= 1) {
#pragma unroll
            for (int j = k >> 1; j > 0; j >>= 1) {
                float ov = __shfl_xor_sync(~0u, v,   j);
                int   oi = __shfl_xor_sync(~0u, idx, j);
                bool down   = ((lane & k) == 0);
                bool lower  = ((lane & j) == 0);
                bool ofirst = (ov > v) || (ov == v && oi < idx);
                bool keep_other = down ? (lower == ofirst) : (lower != ofirst);
                if (keep_other) { v = ov; idx = oi; }
            }
        }

        // inclusive cumsum of sorted probs
        float cum = v;
#pragma unroll
        for (int off = 1; off < 32; off <<= 1) {
            float nb = __shfl_up_sync(~0u, cum, off);
            if (lane >= off) cum += nb;
        }
        unsigned bal = __ballot_sync(~0u, cum >= 0.8f);
        int kk = bal ? __ffs(bal) : 32;
        float sel = __shfl_sync(~0u, cum, kk - 1);
        bool selected = (lane < kk);
        float wv = selected ? (v / sel) : 0.0f;

        // scatter sorted->original expert order via smem
        __syncwarp();
        wsm[idx] = wv;
        ssm[idx] = selected ? 1 : 0;
        __syncwarp();
        float myw = wsm[lane];
        int mysel = ssm[lane];
        unsigned word = __ballot_sync(~0u, mysel != 0);
        __stcs(&g_weights[(size_t)token * EE + lane], myw);
        if (lane == 0) g_mask[token] = word;
        if (lane == 1) g_possum[token] = 0;   // init for scan's atomicAdd
        __syncwarp();
    }
}

// ============================================================
// Kernel 2: per-(b,e) exclusive scan over 4096 tokens,
// capacity truncation, pos_sum accumulation, density count
// ============================================================
__global__ __launch_bounds__(256) void scan_kernel() {
    int e = blockIdx.x & 31;
    int b = blockIdx.x >> 5;
    int tid = threadIdx.x;                // 256 threads, 16 tokens each
    int base = b * GG + tid * 16;

    unsigned bits = 0;
#pragma unroll
    for (int i = 0; i < 16; i++)
        bits |= ((g_mask[base + i] >> e) & 1u) << i;
    int cnt = __popc(bits);

    int lane = tid & 31, wrp = tid >> 5;
    int inc = cnt;
#pragma unroll
    for (int off = 1; off < 32; off <<= 1) {
        int nb = __shfl_up_sync(~0u, inc, off);
        if (lane >= off) inc += nb;
    }
    __shared__ int wsum[8];
    if (lane == 31) wsum[wrp] = inc;
    __syncthreads();
    int wofs = 0, total = 0;
#pragma unroll
    for (int i = 0; i < 8; i++) {
        int v = wsum[i];
        if (i < wrp) wofs += v;
        total += v;
    }
    int run = wofs + inc - cnt;           // exclusive prefix for this thread

    for (int i = 0; i < 16; i++) {
        if ((bits >> i) & 1u) {
            int tok = base + i;
            if (run < CAP) {
                if (run > 0) atomicAdd(&g_possum[tok], run);
            } else {
                atomicAnd(&g_mask[tok], ~(1u << e));   // drop over-capacity
            }
            run++;
        }
    }
    if (tid == 0) g_density[b * EE + e] = (total < CAP) ? total : CAP;
}

// ============================================================
// Kernel 3: scatter for region A only (dispatch offsets < A_FLOATS).
// Runs on stream 0 concurrent with the fused fill (disjoint regions).
// ============================================================
__global__ __launch_bounds__(256) void scatter_A_kernel(float* __restrict__ out) {
    int idx = blockIdx.x * blockDim.x + threadIdx.x;   // token*32 + expert
    int tok = idx >> 5;
    int e   = idx & 31;
    if (tok >= NTOK) return;
    unsigned wm = g_mask[tok];
    if (!((wm >> e) & 1u)) return;
    int ps = g_possum[tok];
    if (ps >= CAP) return;
    size_t o = ((size_t)tok * EE + e) * CAP + ps;
    if (o >= A_FLOATS) return;                // region B handled by fused fill
    out[o] = 1.0f;
}

// ============================================================
// Kernel 4: per-(b,e) proxy sum * density  -> term
// ============================================================
__global__ __launch_bounds__(256) void proxy_kernel() {
    int e = blockIdx.x & 31;
    int b = blockIdx.x >> 5;
    int tid = threadIdx.x;
    float s = 0.0f;
    for (int g = tid; g < GG; g += 256)
        s += __ldcs(&g_probs[((size_t)(b * GG + g)) * EE + e]);
    int lane = tid & 31, wrp = tid >> 5;
#pragma unroll
    for (int off = 16; off; off >>= 1) s += __shfl_xor_sync(~0u, s, off);
    __shared__ float red[8];
    if (lane == 0) red[wrp] = s;
    __syncthreads();
    if (tid == 0) {
        float tot = 0.0f;
#pragma unroll
        for (int i = 0; i < 8; i++) tot += red[i];
        g_term[b * EE + e] = tot * (float)g_density[b * EE + e];
    }
}

// ============================================================
// Kernel 5: final loss = sum(term) * 2^-21  (writes out[2D] only,
// untouched by either fill phase -> runs pre-join)
// ============================================================
__global__ __launch_bounds__(128) void loss_kernel(float* __restrict__ out, size_t D) {
    int tid = threadIdx.x;
    float v = (tid < BB * EE) ? g_term[tid] : 0.0f;
    int lane = tid & 31, wrp = tid >> 5;
#pragma unroll
    for (int off = 16; off; off >>= 1) v += __shfl_xor_sync(~0u, v, off);
    __shared__ float red[4];
    if (lane == 0) red[wrp] = v;
    __syncthreads();
    if (tid == 0) {
        float tot = red[0] + red[1] + red[2] + red[3];
        out[2 * D] = tot * 4.76837158203125e-07f;
    }
}

// ============================================================
extern "C" void kernel_launch(void* const* d_in, const int* in_sizes, int n_in,
                              void* d_out, int out_size) {
    (void)in_sizes; (void)n_in;
    const float* x = (const float*)d_in[0];
    const float* w = (const float*)d_in[1];
    float* out = (float*)d_out;
    size_t D = (size_t)((out_size - 1) / 2);   // dispatch / combine each D elems, loss last

    // region B: [A_FLOATS, 2D) floats -> (2D - A_FLOATS)/8192 blocks (exactly divisible)
    int fusedBlocks = (int)((2 * D - A_FLOATS) / (FILL_TPB * FILL_CHUNK * 4));

    int prLo = 0, prHi = 0;
    cudaDeviceGetStreamPriorityRange(&prLo, &prHi);
    cudaStream_t sZ;
    cudaEvent_t eFork, eA, eC, eDone;
    cudaStreamCreateWithPriority(&sZ, cudaStreamNonBlocking, prHi);
    cudaEventCreateWithFlags(&eFork, cudaEventDisableTiming);
    cudaEventCreateWithFlags(&eA, cudaEventDisableTiming);
    cudaEventCreateWithFlags(&eC, cudaEventDisableTiming);
    cudaEventCreateWithFlags(&eDone, cudaEventDisableTiming);

    // Phase A: blind fill of region A on sZ, concurrent with compute.
    cudaEventRecord(eFork, 0);
    cudaStreamWaitEvent(sZ, eFork, 0);
    fill_kernel<<<A_BLOCKS, FILL_TPB, 0, sZ>>>((float4*)out);
    cudaEventRecord(eA, sZ);

    // Compute chain on main stream (hidden under phase A).
    cudaFuncSetAttribute(gating_kernel,
                         cudaFuncAttributeMaxDynamicSharedMemorySize, TOKS_BLK * HD * 4);
    gating_kernel<<<NTOK / TOKS_BLK, TPB, TOKS_BLK * HD * 4>>>(x, w);
    scan_kernel<<<BB * EE, 256>>>();
    cudaEventRecord(eC, 0);
    proxy_kernel<<<BB * EE, 256>>>();
    loss_kernel<<<1, 128>>>(out, D);          // out[2D] only — independent of fills

    // Phase B: fused fill of region B (zeros + values) after compute.
    cudaStreamWaitEvent(sZ, eC, 0);
    fused_fill_kernel<<<fusedBlocks, FILL_TPB, 0, sZ>>>((float4*)out, (unsigned int)(D / 4));
    cudaEventRecord(eDone, sZ);

    // Region-A scatter on stream 0, concurrent with phase B (disjoint regions).
    cudaStreamWaitEvent(0, eA, 0);
    scatter_A_kernel<<<(NTOK * EE + 255) / 256, 256>>>(out);

    // Join the fork back into the capture stream.
    cudaStreamWaitEvent(0, eDone, 0);

    cudaEventDestroy(eFork);
    cudaEventDestroy(eA);
    cudaEventDestroy(eC);
    cudaEventDestroy(eDone);
    cudaStreamDestroy(sZ);
}